// round 1
// baseline (speedup 1.0000x reference)
#include <cuda_runtime.h>

#define KS     5
#define K2     25
#define DYN    32
#define CSTAT  32
#define NB     4
#define NC     64
#define NH     256
#define NW     256

#define TW     64          // tile width in pixels
#define TH     8           // tile height in pixels
#define PW     4           // pixels per thread along W
#define HALO   2
#define SW     (TW + 2*HALO)   // 68 (multiple of 4 -> float4 alignment holds)
#define SH     (TH + 2*HALO)   // 12
#define CHK    8               // channels staged per chunk
#define NTHR   128             // 16 threads x 8 rows

__global__ __launch_bounds__(NTHR)
void la_kernel(const float* __restrict__ x,
               const float* __restrict__ kern,
               float* __restrict__ out)
{
    __shared__ float sm[CHK * SH * SW];
    __shared__ float skw[K2];

    const int tid = threadIdx.x;
    const int tx  = tid & 15;          // 0..15
    const int ty  = tid >> 4;          // 0..7
    const int w0  = blockIdx.x * TW;
    const int h0  = blockIdx.y * TH;
    const int b   = blockIdx.z;
    const int pw  = w0 + tx * PW;      // first of 4 pixels this thread owns
    const int ph  = h0 + ty;

    if (tid < K2) skw[tid] = kern[tid] * (1.0f / KS);

    float sc[PW][K2];
    #pragma unroll
    for (int p = 0; p < PW; ++p)
        #pragma unroll
        for (int k = 0; k < K2; ++k) sc[p][k] = 0.0f;

    // ================= Phase A: scores over static channels =================
    for (int c0 = CSTAT; c0 < NC; c0 += CHK) {
        __syncthreads();
        {
            const float* src = x + ((long)b * NC + c0) * (NH * NW);
            #pragma unroll 4
            for (int e = tid; e < CHK * SH * SW; e += NTHR) {
                const int ch  = e / (SH * SW);
                const int r   = (e / SW) % SH;
                const int col = e - ch * (SH * SW) - r * SW;
                const int gh  = h0 - HALO + r;
                const int gw  = w0 - HALO + col;
                float v = 0.0f;
                if ((unsigned)gh < NH && (unsigned)gw < NW)
                    v = src[ch * (NH * NW) + gh * NW + gw];
                sm[e] = v;
            }
        }
        __syncthreads();

        #pragma unroll
        for (int cc = 0; cc < CHK; ++cc) {
            const float* chb = &sm[cc * SH * SW];
            // center values for the 4 pixels: row ty+HALO, cols tx*PW+2 .. +5
            float v[PW];
            {
                const float2 cA = *(const float2*)&chb[(ty + HALO) * SW + tx * PW + 2];
                const float2 cB = *(const float2*)&chb[(ty + HALO) * SW + tx * PW + 4];
                v[0] = cA.x; v[1] = cA.y; v[2] = cB.x; v[3] = cB.y;
            }
            #pragma unroll
            for (int i = 0; i < KS; ++i) {
                const float* rp = &chb[(ty + i) * SW + tx * PW];
                const float4 a = *(const float4*)rp;
                const float4 bq = *(const float4*)(rp + 4);
                const float s[8] = {a.x, a.y, a.z, a.w, bq.x, bq.y, bq.z, bq.w};
                #pragma unroll
                for (int j = 0; j < KS; ++j)
                    #pragma unroll
                    for (int p = 0; p < PW; ++p)
                        sc[p][i * KS + j] = fmaf(s[j + p], v[p], sc[p][i * KS + j]);
            }
        }
    }

    // ================= Phase B: scale by kernel weight, softmax =============
    #pragma unroll
    for (int k = 0; k < K2; ++k) {
        const float kw = skw[k];
        #pragma unroll
        for (int p = 0; p < PW; ++p) sc[p][k] *= kw;
    }
    float inv[PW];
    #pragma unroll
    for (int p = 0; p < PW; ++p) {
        float m = sc[p][0];
        #pragma unroll
        for (int k = 1; k < K2; ++k) m = fmaxf(m, sc[p][k]);
        float sum = 0.0f;
        #pragma unroll
        for (int k = 0; k < K2; ++k) {
            const float e = __expf(sc[p][k] - m);
            sc[p][k] = e;
            sum += e;
        }
        inv[p] = 1.0f / sum;
    }

    // ================= Phase C: weighted sum over dynamic channels ==========
    for (int c0 = 0; c0 < DYN; c0 += CHK) {
        __syncthreads();
        {
            const float* src = x + ((long)b * NC + c0) * (NH * NW);
            #pragma unroll 4
            for (int e = tid; e < CHK * SH * SW; e += NTHR) {
                const int ch  = e / (SH * SW);
                const int r   = (e / SW) % SH;
                const int col = e - ch * (SH * SW) - r * SW;
                const int gh  = h0 - HALO + r;
                const int gw  = w0 - HALO + col;
                float v = 0.0f;
                if ((unsigned)gh < NH && (unsigned)gw < NW)
                    v = src[ch * (NH * NW) + gh * NW + gw];
                sm[e] = v;
            }
        }
        __syncthreads();

        #pragma unroll
        for (int cc = 0; cc < CHK; ++cc) {
            const float* chb = &sm[cc * SH * SW];
            float acc[PW] = {0.0f, 0.0f, 0.0f, 0.0f};
            #pragma unroll
            for (int i = 0; i < KS; ++i) {
                const float* rp = &chb[(ty + i) * SW + tx * PW];
                const float4 a = *(const float4*)rp;
                const float4 bq = *(const float4*)(rp + 4);
                const float s[8] = {a.x, a.y, a.z, a.w, bq.x, bq.y, bq.z, bq.w};
                #pragma unroll
                for (int j = 0; j < KS; ++j)
                    #pragma unroll
                    for (int p = 0; p < PW; ++p)
                        acc[p] = fmaf(sc[p][i * KS + j], s[j + p], acc[p]);
            }
            const int c = c0 + cc;
            float4 o;
            o.x = acc[0] * inv[0];
            o.y = acc[1] * inv[1];
            o.z = acc[2] * inv[2];
            o.w = acc[3] * inv[3];
            *(float4*)&out[(((long)b * DYN + c) * NH + ph) * NW + pw] = o;
        }
    }
}

extern "C" void kernel_launch(void* const* d_in, const int* in_sizes, int n_in,
                              void* d_out, int out_size)
{
    const float* x    = (const float*)d_in[0];
    const float* kern = (const float*)d_in[1];
    float* out        = (float*)d_out;
    (void)in_sizes; (void)n_in; (void)out_size;

    dim3 grid(NW / TW, NH / TH, NB);   // (4, 32, 4)
    dim3 block(NTHR);
    la_kernel<<<grid, block>>>(x, kern, out);
}

// round 2
// speedup vs baseline: 2.4861x; 2.4861x over previous
#include <cuda_runtime.h>
#include <cstdint>

#define KS     5
#define K2     25
#define DYN    32
#define NB     4
#define NC     64
#define NH     256
#define NW     256
#define HW     (NH*NW)

#define TW     64
#define TH     8
#define PW     4
#define SW     72                 // logical cols w0-4 .. w0+67 (16B aligned origin)
#define SH     12                 // rows h0-2 .. h0+9
#define CHK    4                  // channels per chunk
#define F4_CH  (SH*(SW/4))        // 216 float4 per channel
#define F4_CK  (CHK*F4_CH)        // 864 float4 per chunk
#define NSLOT  7                  // ceil(864/128)
#define NTHR   128
#define NCHUNK 16                 // 8 static + 8 dynamic
#define BUFS   3

__device__ __forceinline__ void cp_async16(uint32_t saddr, const float* gaddr, unsigned sz)
{
    asm volatile("cp.async.cg.shared.global [%0], [%1], 16, %2;\n"
                 :: "r"(saddr), "l"(gaddr), "r"(sz) : "memory");
}
__device__ __forceinline__ void cp_commit()
{
    asm volatile("cp.async.commit_group;\n" ::: "memory");
}

__global__ __launch_bounds__(NTHR, 3)
void la_kernel(const float* __restrict__ x,
               const float* __restrict__ kern,
               float* __restrict__ out)
{
    __shared__ float4 smbuf[BUFS][F4_CK];   // 3 * 864 * 16B = 40.5 KB
    __shared__ float  skw[K2];

    const int tid = threadIdx.x;
    const int tx  = tid & 15;
    const int ty  = tid >> 4;
    const int w0  = blockIdx.x * TW;
    const int h0  = blockIdx.y * TH;
    const int b   = blockIdx.z;
    const int ph  = h0 + ty;
    const int pw  = w0 + tx * PW;

    if (tid < K2) skw[tid] = kern[tid] * (1.0f / KS);

    // ---- precompute per-thread fill descriptors (chunk-invariant) ----
    int goff[NSLOT];
    #pragma unroll
    for (int s = 0; s < NSLOT; ++s) {
        const int e   = tid + s * NTHR;
        const int ch  = e / F4_CH;
        const int rem = e - ch * F4_CH;
        const int r   = rem / (SW / 4);
        const int j   = rem - r * (SW / 4);
        const int gh  = h0 - 2 + r;
        const int gw0 = w0 - 4 + j * 4;
        const bool ok = ((unsigned)gh < NH) && ((unsigned)gw0 < NW);
        goff[s] = ok ? (ch * HW + gh * NW + gw0) : -1;
    }

    const float* xb = x + (long)b * NC * HW;
    const uint32_t sb0 = (uint32_t)__cvta_generic_to_shared(&smbuf[0][0]);

    // issue chunk 0 (static channels start at 32)
    {
        const float* g = xb + 32 * HW;
        #pragma unroll
        for (int s = 0; s < NSLOT; ++s) {
            const int e = tid + s * NTHR;
            if (s < NSLOT - 1 || e < F4_CK) {
                const int off = goff[s];
                cp_async16(sb0 + (uint32_t)e * 16u,
                           g + (off >= 0 ? off : 0),
                           off >= 0 ? 16u : 0u);
            }
        }
        cp_commit();
    }

    float sc[PW][K2];
    #pragma unroll
    for (int p = 0; p < PW; ++p)
        #pragma unroll
        for (int k = 0; k < K2; ++k) sc[p][k] = 0.0f;

    float inv[PW];

    for (int i = 0; i < NCHUNK; ++i) {
        // ---- issue chunk i+1 into buf[(i+1)%3] ----
        if (i + 1 < NCHUNK) {
            const int cb = (i + 1 < 8) ? (32 + 4 * (i + 1)) : (4 * (i + 1 - 8));
            const float* g = xb + cb * HW;
            const uint32_t sbn = (uint32_t)__cvta_generic_to_shared(&smbuf[(i + 1) % BUFS][0]);
            #pragma unroll
            for (int s = 0; s < NSLOT; ++s) {
                const int e = tid + s * NTHR;
                if (s < NSLOT - 1 || e < F4_CK) {
                    const int off = goff[s];
                    cp_async16(sbn + (uint32_t)e * 16u,
                               g + (off >= 0 ? off : 0),
                               off >= 0 ? 16u : 0u);
                }
            }
            cp_commit();
            asm volatile("cp.async.wait_group 1;\n" ::: "memory");
        } else {
            asm volatile("cp.async.wait_group 0;\n" ::: "memory");
        }
        __syncthreads();

        const float* buf = (const float*)&smbuf[i % BUFS][0];

        if (i < 8) {
            // ============ Phase A: accumulate scores ============
            #pragma unroll
            for (int cc = 0; cc < CHK; ++cc) {
                const float* chb = buf + cc * (SH * SW);
                float v[PW];
                {
                    const float4 cv = *(const float4*)&chb[(ty + 2) * SW + tx * 4 + 4];
                    v[0] = cv.x; v[1] = cv.y; v[2] = cv.z; v[3] = cv.w;
                }
                #pragma unroll
                for (int r = 0; r < KS; ++r) {
                    const float* rp = &chb[(ty + r) * SW + tx * 4];
                    const float4 a = *(const float4*)(rp);
                    const float4 m = *(const float4*)(rp + 4);
                    const float4 c = *(const float4*)(rp + 8);
                    const float s[12] = {a.x, a.y, a.z, a.w, m.x, m.y, m.z, m.w,
                                         c.x, c.y, c.z, c.w};
                    #pragma unroll
                    for (int j = 0; j < KS; ++j)
                        #pragma unroll
                        for (int p = 0; p < PW; ++p)
                            sc[p][r * KS + j] = fmaf(s[2 + j + p], v[p], sc[p][r * KS + j]);
                }
            }
            if (i == 7) {
                // ============ Phase B: softmax ============
                #pragma unroll
                for (int k = 0; k < K2; ++k) {
                    const float kw = skw[k];
                    #pragma unroll
                    for (int p = 0; p < PW; ++p) sc[p][k] *= kw;
                }
                #pragma unroll
                for (int p = 0; p < PW; ++p) {
                    float mx = sc[p][0];
                    #pragma unroll
                    for (int k = 1; k < K2; ++k) mx = fmaxf(mx, sc[p][k]);
                    float sum = 0.0f;
                    #pragma unroll
                    for (int k = 0; k < K2; ++k) {
                        const float e = __expf(sc[p][k] - mx);
                        sc[p][k] = e;
                        sum += e;
                    }
                    inv[p] = 1.0f / sum;
                }
            }
        } else {
            // ============ Phase C: weighted sum of dynamic channels ============
            #pragma unroll
            for (int cc = 0; cc < CHK; ++cc) {
                const float* chb = buf + cc * (SH * SW);
                float acc[PW] = {0.0f, 0.0f, 0.0f, 0.0f};
                #pragma unroll
                for (int r = 0; r < KS; ++r) {
                    const float* rp = &chb[(ty + r) * SW + tx * 4];
                    const float4 a = *(const float4*)(rp);
                    const float4 m = *(const float4*)(rp + 4);
                    const float4 c = *(const float4*)(rp + 8);
                    const float s[12] = {a.x, a.y, a.z, a.w, m.x, m.y, m.z, m.w,
                                         c.x, c.y, c.z, c.w};
                    #pragma unroll
                    for (int j = 0; j < KS; ++j)
                        #pragma unroll
                        for (int p = 0; p < PW; ++p)
                            acc[p] = fmaf(sc[p][r * KS + j], s[2 + j + p], acc[p]);
                }
                const int c = (i - 8) * CHK + cc;
                float4 o;
                o.x = acc[0] * inv[0];
                o.y = acc[1] * inv[1];
                o.z = acc[2] * inv[2];
                o.w = acc[3] * inv[3];
                *(float4*)&out[(((long)b * DYN + c) * NH + ph) * NW + pw] = o;
            }
        }
    }
}

extern "C" void kernel_launch(void* const* d_in, const int* in_sizes, int n_in,
                              void* d_out, int out_size)
{
    const float* x    = (const float*)d_in[0];
    const float* kern = (const float*)d_in[1];
    float* out        = (float*)d_out;
    (void)in_sizes; (void)n_in; (void)out_size;

    dim3 grid(NW / TW, NH / TH, NB);   // (4, 32, 4) = 512 blocks
    dim3 block(NTHR);
    la_kernel<<<grid, block>>>(x, kern, out);
}